// round 1
// baseline (speedup 1.0000x reference)
#include <cuda_runtime.h>
#include <math.h>

// Problem constants
#define NTOK   32768      // B*T = 4*8192
#define DIM    512
#define NOPS   8

// GEMM tiling
#define BM 128
#define BN 128
#define BK 8
#define MAX_TILES 264                 // ceil-sum over 8 groups: <= 256 + 7, pad to 264
#define PERM_SIZE (MAX_TILES * BM)    // 33792

// ---------------- device scratch (no allocations allowed) ----------------
__device__ int g_route[NTOK];
__device__ int g_counts[NOPS];
__device__ int g_cursor[NOPS];
__device__ int g_base[NOPS];
__device__ int g_perm[PERM_SIZE];
__device__ int g_tile_op[MAX_TILES];
__device__ int g_tile_row[MAX_TILES];
__device__ int g_ntiles;

// ---------------- kernels ----------------

__global__ void reset_kernel() {
    int i = blockIdx.x * blockDim.x + threadIdx.x;
    if (i < PERM_SIZE) g_perm[i] = -1;
    if (i < NOPS) { g_counts[i] = 0; g_cursor[i] = 0; }
}

__global__ void route_kernel(const float* __restrict__ logits,
                             const float* __restrict__ gumbel) {
    int t = blockIdx.x * blockDim.x + threadIdx.x;
    if (t >= NTOK) return;
    float best = -INFINITY;
    int bi = 0;
#pragma unroll
    for (int i = 0; i < NOPS; i++) {
        float v = logits[t * NOPS + i] + gumbel[t * NOPS + i];
        if (v > best) { best = v; bi = i; }   // strict > keeps first index on ties (jnp.argmax semantics)
    }
    g_route[t] = bi;
    atomicAdd(&g_counts[bi], 1);
}

// Single-thread scan: build padded group bases + tile metadata.
__global__ void scan_kernel() {
    if (threadIdx.x != 0 || blockIdx.x != 0) return;
    int off = 0, tile = 0;
    for (int g = 0; g < NOPS; g++) {
        g_base[g] = off;
        int cnt = g_counts[g];
        int nt = (cnt + BM - 1) / BM;
        for (int i = 0; i < nt; i++) {
            g_tile_op[tile]  = g;
            g_tile_row[tile] = off + i * BM;
            tile++;
        }
        off += nt * BM;
    }
    g_ntiles = tile;
}

__global__ void scatter_kernel() {
    int t = blockIdx.x * blockDim.x + threadIdx.x;
    if (t >= NTOK) return;
    int op  = g_route[t];
    int pos = atomicAdd(&g_cursor[op], 1);
    g_perm[g_base[op] + pos] = t;
}

__device__ __forceinline__ float apply_act(int op, float h) {
    switch (op) {
        case 0:  return 0.5f * h * (1.0f + erff(h * 0.7071067811865476f)); // exact gelu
        case 1:  return fmaxf(h, 0.0f);                                    // relu
        case 2:  { float r = fmaxf(h, 0.0f); return r * r; }               // relu^2
        case 3:  return h / (1.0f + expf(-h));                             // silu
        case 4:  return tanhf(h);                                          // tanh
        case 5:  return 1.0f / (1.0f + expf(-h));                          // sigmoid
        case 6:  return h;                                                 // identity
        default: return -h;                                                // negate
    }
}

// Grouped SGEMM: C[m][n] = sum_k x[perm[m]][k] * W[op][n][k], activation fused.
// BM=128 x BN=128 x BK=8, 256 threads, 8x8 per-thread microtile.
__global__ __launch_bounds__(256, 2)
void gemm_kernel(const float* __restrict__ x,
                 const float* __restrict__ W,
                 float* __restrict__ out) {
    int bx = blockIdx.x;
    if (bx >= g_ntiles) return;

    const int op   = g_tile_op[bx];
    const int row0 = g_tile_row[bx];
    const int n0   = blockIdx.y * BN;
    const float* __restrict__ Wg = W + (size_t)op * DIM * DIM;

    __shared__ float As[BK][BM];
    __shared__ float Bs[BK][BN];

    const int tid = threadIdx.x;
    // global-load mapping: 256 threads cover 128 rows x (8 floats = 2 float4)
    const int lr = tid >> 1;            // row 0..127
    const int lk = (tid & 1) * 4;       // k sub-offset 0 or 4

    const int tokA = g_perm[row0 + lr];
    const float* aptr = (tokA >= 0) ? (x + (size_t)tokA * DIM + lk) : nullptr;
    const float* bptr = Wg + (size_t)(n0 + lr) * DIM + lk;

    // compute mapping: 16x16 thread grid, each does 8x8
    const int tm0 = (tid >> 4) * 8;
    const int tn0 = (tid & 15) * 8;

    float acc[8][8];
#pragma unroll
    for (int i = 0; i < 8; i++)
#pragma unroll
        for (int j = 0; j < 8; j++) acc[i][j] = 0.0f;

    for (int k0 = 0; k0 < DIM; k0 += BK) {
        float4 av = aptr ? *(const float4*)(aptr + k0) : make_float4(0.f, 0.f, 0.f, 0.f);
        float4 bv = *(const float4*)(bptr + k0);

        __syncthreads();
        As[lk + 0][lr] = av.x; As[lk + 1][lr] = av.y;
        As[lk + 2][lr] = av.z; As[lk + 3][lr] = av.w;
        Bs[lk + 0][lr] = bv.x; Bs[lk + 1][lr] = bv.y;
        Bs[lk + 2][lr] = bv.z; Bs[lk + 3][lr] = bv.w;
        __syncthreads();

#pragma unroll
        for (int k = 0; k < BK; k++) {
            float a[8], b[8];
#pragma unroll
            for (int i = 0; i < 8; i++) a[i] = As[k][tm0 + i];
#pragma unroll
            for (int j = 0; j < 8; j++) b[j] = Bs[k][tn0 + j];
#pragma unroll
            for (int i = 0; i < 8; i++)
#pragma unroll
                for (int j = 0; j < 8; j++)
                    acc[i][j] = fmaf(a[i], b[j], acc[i][j]);
        }
    }

    // epilogue: activation + scatter back to original token rows
#pragma unroll
    for (int i = 0; i < 8; i++) {
        int tok = g_perm[row0 + tm0 + i];
        if (tok < 0) continue;
        float* o = out + (size_t)tok * DIM + n0 + tn0;
        float4 v0, v1;
        v0.x = apply_act(op, acc[i][0]);
        v0.y = apply_act(op, acc[i][1]);
        v0.z = apply_act(op, acc[i][2]);
        v0.w = apply_act(op, acc[i][3]);
        v1.x = apply_act(op, acc[i][4]);
        v1.y = apply_act(op, acc[i][5]);
        v1.z = apply_act(op, acc[i][6]);
        v1.w = apply_act(op, acc[i][7]);
        *(float4*)(o)     = v0;
        *(float4*)(o + 4) = v1;
    }
}

// ---------------- launch ----------------
extern "C" void kernel_launch(void* const* d_in, const int* in_sizes, int n_in,
                              void* d_out, int out_size) {
    const float* x      = (const float*)d_in[0];  // (B,T,DIM)
    const float* logits = (const float*)d_in[1];  // (B,T,8)
    const float* gumbel = (const float*)d_in[2];  // (B,T,8)
    const float* W      = (const float*)d_in[3];  // (8,512,512)
    float* out          = (float*)d_out;          // (B,T,DIM)

    reset_kernel<<<(PERM_SIZE + 255) / 256, 256>>>();
    route_kernel<<<(NTOK + 255) / 256, 256>>>(logits, gumbel);
    scan_kernel<<<1, 32>>>();
    scatter_kernel<<<(NTOK + 255) / 256, 256>>>();

    dim3 grid(MAX_TILES, DIM / BN);
    gemm_kernel<<<grid, 256>>>(x, W, out);
}

// round 4
// speedup vs baseline: 2.5059x; 2.5059x over previous
#include <cuda_runtime.h>
#include <cuda_bf16.h>
#include <math.h>
#include <stdint.h>

// Problem constants
#define NTOK   32768
#define DIM    512
#define NOPS   8

// GEMM tiling
#define BM 128
#define BN 128
#define BK 64                  // k elems per chunk = 128 bytes/row (SW128 atom)
#define NCHUNK (DIM / BK)      // 8
#define NPASS 3                // hi*hi, hi*lo, lo*hi
#define NITER (NPASS * NCHUNK) // 24
#define MAX_TILES 264
#define PERM_SIZE (MAX_TILES * BM)

// SMEM (bytes, relative to 1024-aligned base): A[2] then B[2], 16KB each
#define SMEM_A0 0
#define SMEM_A1 16384
#define SMEM_B0 32768
#define SMEM_B1 49152
#define SMEM_DYN (65536 + 1024)

#define SW128(o) ((o) ^ (((o) >> 3) & 0x70))

// ---------------- device scratch ----------------
__device__ int g_route[NTOK];
__device__ int g_counts[NOPS];
__device__ int g_cursor[NOPS];
__device__ int g_base[NOPS];
__device__ int g_perm[PERM_SIZE];
__device__ int g_tile_op[MAX_TILES];
__device__ int g_tile_row[MAX_TILES];
__device__ int g_ntiles;

__device__ __nv_bfloat16 g_Whi[NOPS * DIM * DIM];
__device__ __nv_bfloat16 g_Wlo[NOPS * DIM * DIM];
__device__ __nv_bfloat16 g_Ahi[(size_t)PERM_SIZE * DIM];
__device__ __nv_bfloat16 g_Alo[(size_t)PERM_SIZE * DIM];

// ---------------- PTX helpers ----------------
__device__ __forceinline__ uint32_t smem_u32(const void* p) {
    uint32_t a;
    asm("{ .reg .u64 t; cvta.to.shared.u64 t, %1; cvt.u32.u64 %0, t; }" : "=r"(a) : "l"(p));
    return a;
}
__device__ __forceinline__ void cp_async16(uint32_t dst, const void* src) {
    asm volatile("cp.async.cg.shared.global [%0], [%1], 16;" :: "r"(dst), "l"(src) : "memory");
}
__device__ __forceinline__ void cp_commit() {
    asm volatile("cp.async.commit_group;" ::: "memory");
}
template <int N>
__device__ __forceinline__ void cp_wait() {
    asm volatile("cp.async.wait_group %0;" :: "n"(N) : "memory");
}
__device__ __forceinline__ void ldsm_x4(uint32_t& r0, uint32_t& r1, uint32_t& r2, uint32_t& r3,
                                        uint32_t addr) {
    asm volatile("ldmatrix.sync.aligned.m8n8.x4.shared.b16 {%0,%1,%2,%3}, [%4];"
                 : "=r"(r0), "=r"(r1), "=r"(r2), "=r"(r3) : "r"(addr));
}
__device__ __forceinline__ void hmma(float* c, uint32_t a0, uint32_t a1, uint32_t a2, uint32_t a3,
                                     uint32_t b0, uint32_t b1) {
    asm volatile(
        "mma.sync.aligned.m16n8k16.row.col.f32.bf16.bf16.f32 "
        "{%0,%1,%2,%3}, {%4,%5,%6,%7}, {%8,%9}, {%0,%1,%2,%3};"
        : "+f"(c[0]), "+f"(c[1]), "+f"(c[2]), "+f"(c[3])
        : "r"(a0), "r"(a1), "r"(a2), "r"(a3), "r"(b0), "r"(b1));
}

// ---------------- aux kernels ----------------

__global__ void resetw_kernel(const float* __restrict__ W) {
    int i = blockIdx.x * blockDim.x + threadIdx.x;    // 0 .. 524287
    if (i < PERM_SIZE) g_perm[i] = -1;
    if (i < NOPS) { g_counts[i] = 0; g_cursor[i] = 0; }
    float4 w = ((const float4*)W)[i];
    float in[4] = {w.x, w.y, w.z, w.w};
    __nv_bfloat16 hb[4], lb[4];
#pragma unroll
    for (int j = 0; j < 4; j++) {
        hb[j] = __float2bfloat16(in[j]);
        lb[j] = __float2bfloat16(in[j] - __bfloat162float(hb[j]));
    }
    *(uint2*)&g_Whi[(size_t)i * 4] = *(uint2*)hb;
    *(uint2*)&g_Wlo[(size_t)i * 4] = *(uint2*)lb;
}

__global__ void route_kernel(const float* __restrict__ logits,
                             const float* __restrict__ gumbel) {
    int t = blockIdx.x * blockDim.x + threadIdx.x;
    if (t >= NTOK) return;
    float best = -INFINITY;
    int bi = 0;
#pragma unroll
    for (int i = 0; i < NOPS; i++) {
        float v = logits[t * NOPS + i] + gumbel[t * NOPS + i];
        if (v > best) { best = v; bi = i; }
    }
    g_route[t] = bi;
    atomicAdd(&g_counts[bi], 1);
}

__global__ void scan_kernel() {
    if (threadIdx.x != 0 || blockIdx.x != 0) return;
    int off = 0, tile = 0;
    for (int g = 0; g < NOPS; g++) {
        g_base[g] = off;
        int cnt = g_counts[g];
        int nt = (cnt + BM - 1) / BM;
        for (int i = 0; i < nt; i++) {
            g_tile_op[tile] = g;
            g_tile_row[tile] = off + i * BM;
            tile++;
        }
        off += nt * BM;
    }
    g_ntiles = tile;
}

__global__ void scatter_kernel() {
    int t = blockIdx.x * blockDim.x + threadIdx.x;
    if (t >= NTOK) return;
    int op = g_route[t];
    int pos = atomicAdd(&g_cursor[op], 1);
    g_perm[g_base[op] + pos] = t;
}

__global__ void aconvert_kernel(const float* __restrict__ x) {
    int idx = blockIdx.x * blockDim.x + threadIdx.x;
    int row = idx >> 7;
    int c4  = idx & 127;
    int tok = g_perm[row];
    __nv_bfloat16 hb[4], lb[4];
    if (tok >= 0) {
        float4 v = ((const float4*)(x + (size_t)tok * DIM))[c4];
        float in[4] = {v.x, v.y, v.z, v.w};
#pragma unroll
        for (int j = 0; j < 4; j++) {
            hb[j] = __float2bfloat16(in[j]);
            lb[j] = __float2bfloat16(in[j] - __bfloat162float(hb[j]));
        }
    } else {
#pragma unroll
        for (int j = 0; j < 4; j++) { hb[j] = __float2bfloat16(0.f); lb[j] = __float2bfloat16(0.f); }
    }
    size_t o = (size_t)row * DIM + c4 * 4;
    *(uint2*)&g_Ahi[o] = *(uint2*)hb;
    *(uint2*)&g_Alo[o] = *(uint2*)lb;
}

__device__ __forceinline__ float apply_act(int op, float h) {
    switch (op) {
        case 0:  return 0.5f * h * (1.0f + erff(h * 0.7071067811865476f));
        case 1:  return fmaxf(h, 0.0f);
        case 2:  { float r = fmaxf(h, 0.0f); return r * r; }
        case 3:  return h / (1.0f + expf(-h));
        case 4:  return tanhf(h);
        case 5:  return 1.0f / (1.0f + expf(-h));
        case 6:  return h;
        default: return -h;
    }
}

// ---------------- HMMA grouped GEMM ----------------
// 256 threads = 8 warps (2 M x 4 N), warp tile 64x32, cp.async double buffer.
__global__ __launch_bounds__(256)
void gemm_kernel(float* __restrict__ out) {
    extern __shared__ char dsm[];
    const int bx = blockIdx.x;
    if (bx >= g_ntiles) return;

    const int op   = g_tile_op[bx];
    const int row0 = g_tile_row[bx];
    const int n0   = blockIdx.y * BN;
    const int tid  = threadIdx.x;
    const int wid  = tid >> 5;
    const int lid  = tid & 31;
    const int wm   = wid >> 2;     // 0..1
    const int wn   = wid & 3;      // 0..3

    char* sbase = (char*)(((uintptr_t)dsm + 1023) & ~(uintptr_t)1023);
    const uint32_t sb = smem_u32(sbase);

    const __nv_bfloat16* __restrict__ Wh = g_Whi + (size_t)op * DIM * DIM;
    const __nv_bfloat16* __restrict__ Wl = g_Wlo + (size_t)op * DIM * DIM;
    const __nv_bfloat16* Apass[NPASS] = {g_Ahi, g_Ahi, g_Alo};
    const __nv_bfloat16* Bpass[NPASS] = {Wh, Wl, Wh};

    // store mapping: 1024 16B units; r = sid>>3 (row), ks = sid&7 (16B col)
    const int lr = tid >> 3;
    const int ks = tid & 7;
    const uint32_t sw_col = (uint32_t)(ks * 16);

    // ldmatrix addressing: addr = row_base + (col ^ mask), mask = (row&7)<<4.
    // A: rows m = wm*64 + mi*16 + (lid&15); col = (lid>>4)*16 + kk*32
    const int a_row = wm * 64 + (lid & 15);
    const uint32_t a_rowbase = sb + SMEM_A0 + (uint32_t)(a_row * 128);
    const uint32_t a_mask = (uint32_t)((a_row & 7) << 4);
    const uint32_t a_col0 = (uint32_t)((lid >> 4) << 4);
    // B: rows n = wn*32 + nb*16 + (lid&7) + ((lid>>4)<<3); col = ((lid>>3)&1)*16 + kk*32
    const int b_row = wn * 32 + (lid & 7) + ((lid >> 4) << 3);
    const uint32_t b_rowbase = sb + SMEM_B0 + (uint32_t)(b_row * 128);
    const uint32_t b_mask = (uint32_t)((b_row & 7) << 4);
    const uint32_t b_col0 = (uint32_t)(((lid >> 3) & 1) << 4);

    float acc[4][4][4];
#pragma unroll
    for (int i = 0; i < 4; i++)
#pragma unroll
        for (int j = 0; j < 4; j++)
#pragma unroll
            for (int q = 0; q < 4; q++) acc[i][j][q] = 0.0f;

    auto load_chunk = [&](int c, int s) {
        const int p  = c >> 3;
        const int kc = c & 7;
        const __nv_bfloat16* Ag = Apass[p] + (size_t)row0 * DIM + kc * BK;
        const __nv_bfloat16* Bg = Bpass[p] + (size_t)n0 * DIM + kc * BK;
        const uint32_t As = sb + (s ? SMEM_A1 : SMEM_A0);
        const uint32_t Bs = sb + (s ? SMEM_B1 : SMEM_B0);
#pragma unroll
        for (int j = 0; j < 4; j++) {
            int r = lr + j * 32;
            uint32_t soff = SW128((uint32_t)(r * 128) + sw_col);
            cp_async16(As + soff, Ag + (size_t)r * DIM + ks * 8);
            cp_async16(Bs + soff, Bg + (size_t)r * DIM + ks * 8);
        }
        cp_commit();
    };

    load_chunk(0, 0);
    load_chunk(1, 1);

    for (int i = 0; i < NITER; i++) {
        const int s = i & 1;
        cp_wait<1>();
        __syncthreads();

        const uint32_t As_base = a_rowbase + (s ? SMEM_A1 : 0);
        const uint32_t Bs_base = b_rowbase + (s ? (SMEM_B1 - SMEM_B0) : 0);

#pragma unroll
        for (int kk = 0; kk < 4; kk++) {                 // 4 x k16 per chunk
            const uint32_t a_col = (a_col0 + kk * 32) ^ a_mask;
            const uint32_t b_col = (b_col0 + kk * 32) ^ b_mask;
            uint32_t a[4][4];
            uint32_t b[4][2];
#pragma unroll
            for (int mi = 0; mi < 4; mi++)
                ldsm_x4(a[mi][0], a[mi][1], a[mi][2], a[mi][3],
                        As_base + mi * (16 * 128) + a_col);
#pragma unroll
            for (int nb = 0; nb < 2; nb++)
                ldsm_x4(b[nb * 2][0], b[nb * 2][1], b[nb * 2 + 1][0], b[nb * 2 + 1][1],
                        Bs_base + nb * (16 * 128) + b_col);
#pragma unroll
            for (int mi = 0; mi < 4; mi++)
#pragma unroll
                for (int ni = 0; ni < 4; ni++)
                    hmma(acc[mi][ni], a[mi][0], a[mi][1], a[mi][2], a[mi][3],
                         b[ni][0], b[ni][1]);
        }

        __syncthreads();
        if (i + 2 < NITER) load_chunk(i + 2, s);
        else cp_commit();   // keep group count consistent for cp_wait<1>
    }

    // epilogue: activation + scatter to original token rows
    const int r = lid >> 2;
    const int c = (lid & 3) * 2;
#pragma unroll
    for (int mi = 0; mi < 4; mi++) {
        const int m_lo = wm * 64 + mi * 16 + r;
        const int tok_lo = g_perm[row0 + m_lo];
        const int tok_hi = g_perm[row0 + m_lo + 8];
        float* o_lo = (tok_lo >= 0) ? (out + (size_t)tok_lo * DIM + n0) : nullptr;
        float* o_hi = (tok_hi >= 0) ? (out + (size_t)tok_hi * DIM + n0) : nullptr;
#pragma unroll
        for (int ni = 0; ni < 4; ni++) {
            const int n = wn * 32 + ni * 8 + c;
            if (o_lo) {
                float2 v;
                v.x = apply_act(op, acc[mi][ni][0]);
                v.y = apply_act(op, acc[mi][ni][1]);
                *(float2*)(o_lo + n) = v;
            }
            if (o_hi) {
                float2 v;
                v.x = apply_act(op, acc[mi][ni][2]);
                v.y = apply_act(op, acc[mi][ni][3]);
                *(float2*)(o_hi + n) = v;
            }
        }
    }
}

// ---------------- launch ----------------
extern "C" void kernel_launch(void* const* d_in, const int* in_sizes, int n_in,
                              void* d_out, int out_size) {
    const float* x      = (const float*)d_in[0];
    const float* logits = (const float*)d_in[1];
    const float* gumbel = (const float*)d_in[2];
    const float* W      = (const float*)d_in[3];
    float* out          = (float*)d_out;

    cudaFuncSetAttribute(gemm_kernel, cudaFuncAttributeMaxDynamicSharedMemorySize, SMEM_DYN);

    resetw_kernel<<<(NOPS * DIM * DIM / 4 + 255) / 256, 256>>>(W);
    route_kernel<<<(NTOK + 255) / 256, 256>>>(logits, gumbel);
    scan_kernel<<<1, 32>>>();
    scatter_kernel<<<(NTOK + 255) / 256, 256>>>();
    aconvert_kernel<<<(PERM_SIZE * (DIM / 4) + 255) / 256, 256>>>(x);

    dim3 grid(MAX_TILES, DIM / BN);
    gemm_kernel<<<grid, 256, SMEM_DYN>>>(out);
}